// round 7
// baseline (speedup 1.0000x reference)
#include <cuda_runtime.h>
#include <cuda_bf16.h>

// ---------------------------------------------------------------------------
// MHCLayerAITER fused single-kernel.
// out[b,i,c] = sum_j M[i][j]*x[b,j,c] + 2*sig(H_post[i]) * y[b,c]
//   y[b,c]   = bf16(x_agg[b,c]) / rms_b * bf16(w[c])
//   x_agg    = sum_n sig(H_pre[n]) * x[b,n,c]
//   rms_b    = sqrt(mean_c bf16(x_agg)^2 + 1e-6)
//   M        = sinkhorn_knopp(exp(H_res), 3 iters, eps=1e-6)
// B=8192, n=4, C=2048. HBM-bound: 268MB in + 268MB out.
//
// Configuration = R4's measured-best kernel body (256 threads, kVec=2 ->
// 8 front-batched float4 LDGs per thread, plain caching) + in-kernel Sinkhorn
// prologue (warp 0, shuffle butterflies) placed BEFORE the loads with a
// barrier so its temporaries never overlap the x register tile.
// ---------------------------------------------------------------------------

namespace {
constexpr int kB = 8192;
constexpr int kN = 4;
constexpr int kC = 2048;
constexpr int kThreads = 256;
constexpr int kC4 = kC / 4;            // 512 float4 per stream per row
constexpr int kVec = kC4 / kThreads;   // 2 float4 chunks per thread
constexpr float kEps = 1e-6f;
}

__global__ __launch_bounds__(kThreads) void mhc_fused_kernel(
    const float4* __restrict__ x,      // [B, n, C/4]
    const float4* __restrict__ w,      // [C/4]
    const float*  __restrict__ H_pre,  // [4]
    const float*  __restrict__ H_post, // [4]
    const float*  __restrict__ H_res,  // [4,4]
    float4* __restrict__ out) {        // [B, n, C/4]
    const int b = blockIdx.x;
    const int t = threadIdx.x;

    __shared__ float s_params[24];     // M[16] | sig(H_pre)[4] | 2*sig(H_post)[4]
    __shared__ float s_warp[kThreads / 32];
    __shared__ float s_rinv;

    // ---- Phase 0 (warp 0): Sinkhorn-Knopp on exp(H_res) + activations.
    // Lane l (<16) owns P[l/4][l%4]. Row sums via butterfly offsets {1,2},
    // column sums via {4,8}. Lanes 16-31 run with p=1; their butterflies stay
    // in the upper half. All temporaries are dead at the barrier below, so
    // this adds no register pressure to the streaming phase.
    if (t < 32) {
        const int lane = t;
        float h = (lane < 16) ? H_res[lane] : 0.0f;
        float p = expf(h);
#pragma unroll
        for (int it = 0; it < 3; ++it) {
            float s = p;
            s += __shfl_xor_sync(0xFFFFFFFFu, s, 1);
            s += __shfl_xor_sync(0xFFFFFFFFu, s, 2);
            p = p / (s + kEps);          // row normalize
            s = p;
            s += __shfl_xor_sync(0xFFFFFFFFu, s, 4);
            s += __shfl_xor_sync(0xFFFFFFFFu, s, 8);
            p = p / (s + kEps);          // column normalize
        }
        if (lane < 16) {
            s_params[lane] = p;
        } else if (lane < 20) {
            s_params[lane] = 1.0f / (1.0f + expf(-H_pre[lane - 16]));
        } else if (lane < 24) {
            s_params[lane] = 2.0f / (1.0f + expf(-H_post[lane - 20]));
        }
    }
    __syncthreads();

    const size_t base = (size_t)b * (kN * kC4);

    // ---- Phase 1: front-batched loads — all 4 streams, 8 float4 LDGs -------
    float xr[kN][kVec * 4];
#pragma unroll
    for (int k = 0; k < kVec; ++k) {
        const int c4 = t + k * kThreads;
#pragma unroll
        for (int n = 0; n < kN; ++n) {
            float4 v = x[base + (size_t)n * kC4 + c4];
            xr[n][k * 4 + 0] = v.x;
            xr[n][k * 4 + 1] = v.y;
            xr[n][k * 4 + 2] = v.z;
            xr[n][k * 4 + 3] = v.w;
        }
    }

    // ---- Weight (L2/L1-resident after first wave; bf16-round per ref) ------
    float wr[kVec * 4];
#pragma unroll
    for (int k = 0; k < kVec; ++k) {
        float4 wv = w[t + k * kThreads];
        wr[k * 4 + 0] = __bfloat162float(__float2bfloat16_rn(wv.x));
        wr[k * 4 + 1] = __bfloat162float(__float2bfloat16_rn(wv.y));
        wr[k * 4 + 2] = __bfloat162float(__float2bfloat16_rn(wv.z));
        wr[k * 4 + 3] = __bfloat162float(__float2bfloat16_rn(wv.w));
    }

    // ---- Params from smem (LDS broadcast, after LDGs are in flight) --------
    float M[4][4], hpre[4], hpost[4];
#pragma unroll
    for (int i = 0; i < 4; ++i)
#pragma unroll
        for (int j = 0; j < 4; ++j)
            M[i][j] = s_params[i * 4 + j];
#pragma unroll
    for (int n = 0; n < 4; ++n) hpre[n] = s_params[16 + n];
#pragma unroll
    for (int n = 0; n < 4; ++n) hpost[n] = s_params[20 + n];

    // ---- Phase 2: aggregate streams; round through bf16; sum of squares ----
    float aggb[kVec * 4];
    float lsum = 0.0f;
#pragma unroll
    for (int e = 0; e < kVec * 4; ++e) {
        float a = 0.0f;
#pragma unroll
        for (int n = 0; n < kN; ++n)
            a = fmaf(hpre[n], xr[n][e], a);
        float ab = __bfloat162float(__float2bfloat16_rn(a));
        aggb[e] = ab;
        lsum = fmaf(ab, ab, lsum);
    }

    // ---- Phase 3: block reduction over C=2048 -------------------------------
#pragma unroll
    for (int off = 16; off > 0; off >>= 1)
        lsum += __shfl_xor_sync(0xFFFFFFFFu, lsum, off);

    const int wid = t >> 5;
    const int lane = t & 31;
    if (lane == 0) s_warp[wid] = lsum;
    __syncthreads();
    if (t == 0) {
        float s = 0.0f;
#pragma unroll
        for (int i = 0; i < kThreads / 32; ++i) s += s_warp[i];
        float rms = sqrtf(s * (1.0f / (float)kC) + kEps);
        s_rinv = 1.0f / rms;
    }
    __syncthreads();
    const float rinv = s_rinv;

    // ---- Phase 4: y_norm and output -----------------------------------------
    float y[kVec * 4];
#pragma unroll
    for (int e = 0; e < kVec * 4; ++e)
        y[e] = aggb[e] * rinv * wr[e];

#pragma unroll
    for (int i = 0; i < kN; ++i) {
#pragma unroll
        for (int k = 0; k < kVec; ++k) {
            const int c4 = t + k * kThreads;
            float4 o;
            float r[4];
#pragma unroll
            for (int q = 0; q < 4; ++q) {
                const int e = k * 4 + q;
                float acc = hpost[i] * y[e];
#pragma unroll
                for (int j = 0; j < kN; ++j)
                    acc = fmaf(M[i][j], xr[j][e], acc);
                r[q] = acc;
            }
            o.x = r[0]; o.y = r[1]; o.z = r[2]; o.w = r[3];
            out[base + (size_t)i * kC4 + c4] = o;
        }
    }
}

// ---------------------------------------------------------------------------
// Launch. Inputs (metadata order): x, rmsnorm_weight, H_pre, H_post, H_res.
// Single graph node.
// ---------------------------------------------------------------------------
extern "C" void kernel_launch(void* const* d_in, const int* in_sizes, int n_in,
                              void* d_out, int out_size) {
    const float* x      = (const float*)d_in[0];
    const float* w      = (const float*)d_in[1];
    const float* H_pre  = (const float*)d_in[2];
    const float* H_post = (const float*)d_in[3];
    const float* H_res  = (const float*)d_in[4];
    float* out = (float*)d_out;

    mhc_fused_kernel<<<kB, kThreads>>>(
        (const float4*)x, (const float4*)w, H_pre, H_post, H_res,
        (float4*)out);
}

// round 8
// speedup vs baseline: 1.0489x; 1.0489x over previous
#include <cuda_runtime.h>
#include <cuda_bf16.h>

// ---------------------------------------------------------------------------
// MHCLayerAITER fused single-kernel, register-capped.
// out[b,i,c] = sum_j M[i][j]*x[b,j,c] + 2*sig(H_post[i]) * y[b,c]
//   y[b,c]   = bf16(x_agg[b,c]) / rms_b * bf16(w[c])
//   x_agg    = sum_n sig(H_pre[n]) * x[b,n,c]
//   rms_b    = sqrt(mean_c bf16(x_agg)^2 + 1e-6)
//   M        = sinkhorn_knopp(exp(H_res), 3 iters, eps=1e-6)
// B=8192, n=4, C=2048. HBM-bound: 268MB in + 268MB out.
//
// The decisive variable across rounds is resident warps: 64 regs -> 4 CTAs/SM
// -> 32 warps -> ~80% DRAM; 80 regs -> 3 CTAs -> 24 warps -> ~72% DRAM.
// __launch_bounds__(256, 4) pins the 64-reg allocation. Pressure is kept
// under the cap by loading w after the reduction and reading M from smem
// row-at-a-time in the epilogue.
// ---------------------------------------------------------------------------

namespace {
constexpr int kB = 8192;
constexpr int kN = 4;
constexpr int kC = 2048;
constexpr int kThreads = 256;
constexpr int kC4 = kC / 4;            // 512 float4 per stream per row
constexpr int kVec = kC4 / kThreads;   // 2 float4 chunks per thread
constexpr float kEps = 1e-6f;
}

__global__ __launch_bounds__(kThreads, 4) void mhc_fused_kernel(
    const float4* __restrict__ x,      // [B, n, C/4]
    const float4* __restrict__ w,      // [C/4]
    const float*  __restrict__ H_pre,  // [4]
    const float*  __restrict__ H_post, // [4]
    const float*  __restrict__ H_res,  // [4,4]
    float4* __restrict__ out) {        // [B, n, C/4]
    const int b = blockIdx.x;
    const int t = threadIdx.x;

    __shared__ float s_params[24];     // M[16] | sig(H_pre)[4] | 2*sig(H_post)[4]
    __shared__ float s_warp[kThreads / 32];
    __shared__ float s_rinv;

    // ---- Phase 0 (warp 0): Sinkhorn-Knopp on exp(H_res) + activations.
    // Lane l (<16) owns P[l/4][l%4]. Row sums via butterfly offsets {1,2},
    // column sums via {4,8}. Lanes 16-31 run with p=1; their butterflies
    // stay in the upper half and never pollute lanes 0-15.
    if (t < 32) {
        const int lane = t;
        float h = (lane < 16) ? H_res[lane] : 0.0f;
        float p = expf(h);
#pragma unroll
        for (int it = 0; it < 3; ++it) {
            float s = p;
            s += __shfl_xor_sync(0xFFFFFFFFu, s, 1);
            s += __shfl_xor_sync(0xFFFFFFFFu, s, 2);
            p = p / (s + kEps);          // row normalize
            s = p;
            s += __shfl_xor_sync(0xFFFFFFFFu, s, 4);
            s += __shfl_xor_sync(0xFFFFFFFFu, s, 8);
            p = p / (s + kEps);          // column normalize
        }
        if (lane < 16) {
            s_params[lane] = p;
        } else if (lane < 20) {
            s_params[lane] = 1.0f / (1.0f + expf(-H_pre[lane - 16]));
        } else if (lane < 24) {
            s_params[lane] = 2.0f / (1.0f + expf(-H_post[lane - 20]));
        }
    }
    __syncthreads();

    const size_t base = (size_t)b * (kN * kC4);

    // ---- Phase 1: front-batched loads — all 4 streams, 8 float4 LDGs -------
    float xr[kN][kVec * 4];
#pragma unroll
    for (int k = 0; k < kVec; ++k) {
        const int c4 = t + k * kThreads;
#pragma unroll
        for (int n = 0; n < kN; ++n) {
            float4 v = x[base + (size_t)n * kC4 + c4];
            xr[n][k * 4 + 0] = v.x;
            xr[n][k * 4 + 1] = v.y;
            xr[n][k * 4 + 2] = v.z;
            xr[n][k * 4 + 3] = v.w;
        }
    }

    // ---- Phase 2: aggregate streams (hpre from smem, short-lived regs);
    //      round through bf16; accumulate sum of squares. y[] holds bf16(agg)
    //      for now and is finished in place after the reduction.
    float y[kVec * 4];
    float lsum = 0.0f;
    {
        const float hp0 = s_params[16];
        const float hp1 = s_params[17];
        const float hp2 = s_params[18];
        const float hp3 = s_params[19];
#pragma unroll
        for (int e = 0; e < kVec * 4; ++e) {
            float a = hp0 * xr[0][e];
            a = fmaf(hp1, xr[1][e], a);
            a = fmaf(hp2, xr[2][e], a);
            a = fmaf(hp3, xr[3][e], a);
            float ab = __bfloat162float(__float2bfloat16_rn(a));
            y[e] = ab;
            lsum = fmaf(ab, ab, lsum);
        }
    }

    // ---- Phase 3: block reduction over C=2048 -------------------------------
#pragma unroll
    for (int off = 16; off > 0; off >>= 1)
        lsum += __shfl_xor_sync(0xFFFFFFFFu, lsum, off);

    const int wid = t >> 5;
    const int lane = t & 31;
    if (lane == 0) s_warp[wid] = lsum;
    __syncthreads();
    if (t == 0) {
        float s = 0.0f;
#pragma unroll
        for (int i = 0; i < kThreads / 32; ++i) s += s_warp[i];
        float rms = sqrtf(s * (1.0f / (float)kC) + kEps);
        s_rinv = 1.0f / rms;
    }
    __syncthreads();
    const float rinv = s_rinv;

    // ---- Phase 4: finish y in place. w loaded here (L1/L2-resident by now),
    //      so its registers overlap the dead aggregation temps.
#pragma unroll
    for (int k = 0; k < kVec; ++k) {
        float4 wv = w[t + k * kThreads];
        y[k * 4 + 0] *= rinv * __bfloat162float(__float2bfloat16_rn(wv.x));
        y[k * 4 + 1] *= rinv * __bfloat162float(__float2bfloat16_rn(wv.y));
        y[k * 4 + 2] *= rinv * __bfloat162float(__float2bfloat16_rn(wv.z));
        y[k * 4 + 3] *= rinv * __bfloat162float(__float2bfloat16_rn(wv.w));
    }

    // ---- Phase 5: mix + combine. One M row (+hpost) live at a time ----------
#pragma unroll
    for (int i = 0; i < kN; ++i) {
        const float m0 = s_params[i * 4 + 0];
        const float m1 = s_params[i * 4 + 1];
        const float m2 = s_params[i * 4 + 2];
        const float m3 = s_params[i * 4 + 3];
        const float hpost_i = s_params[20 + i];
#pragma unroll
        for (int k = 0; k < kVec; ++k) {
            const int c4 = t + k * kThreads;
            float r[4];
#pragma unroll
            for (int q = 0; q < 4; ++q) {
                const int e = k * 4 + q;
                float acc = hpost_i * y[e];
                acc = fmaf(m0, xr[0][e], acc);
                acc = fmaf(m1, xr[1][e], acc);
                acc = fmaf(m2, xr[2][e], acc);
                acc = fmaf(m3, xr[3][e], acc);
                r[q] = acc;
            }
            float4 o;
            o.x = r[0]; o.y = r[1]; o.z = r[2]; o.w = r[3];
            out[base + (size_t)i * kC4 + c4] = o;
        }
    }
}

// ---------------------------------------------------------------------------
// Launch. Inputs (metadata order): x, rmsnorm_weight, H_pre, H_post, H_res.
// Single graph node.
// ---------------------------------------------------------------------------
extern "C" void kernel_launch(void* const* d_in, const int* in_sizes, int n_in,
                              void* d_out, int out_size) {
    const float* x      = (const float*)d_in[0];
    const float* w      = (const float*)d_in[1];
    const float* H_pre  = (const float*)d_in[2];
    const float* H_post = (const float*)d_in[3];
    const float* H_res  = (const float*)d_in[4];
    float* out = (float*)d_out;

    mhc_fused_kernel<<<kB, kThreads>>>(
        (const float4*)x, (const float4*)w, H_pre, H_post, H_res,
        (float4*)out);
}

// round 10
// speedup vs baseline: 1.0610x; 1.0115x over previous
#include <cuda_runtime.h>
#include <cuda_bf16.h>

// ---------------------------------------------------------------------------
// MHCLayerAITER fused single-kernel, barrier-free prologue.
// out[b,i,c] = sum_j M[i][j]*x[b,j,c] + 2*sig(H_post[i]) * y[b,c]
//   y[b,c]   = bf16(x_agg[b,c]) / rms_b * bf16(w[c])
//   x_agg    = sum_n sig(H_pre[n]) * x[b,n,c]
//   rms_b    = sqrt(mean_c bf16(x_agg)^2 + 1e-6)
//   M        = sinkhorn_knopp(exp(H_res), 3 iters, eps=1e-6)
// B=8192, n=4, C=2048. HBM-bound: 268MB in + 268MB out.
//
// Every warp computes the 4x4 Sinkhorn redundantly via shuffle butterflies —
// no prologue barrier, no smem for params — so the 8 front-batched x LDGs are
// the first thing each block issues and the param math hides behind them.
// Single barrier total (the rms reduction); all threads redundantly finish
// the reduction to avoid a second barrier.
// (Resubmission of R9 source — previous round was an infra failure, the
// kernel never ran.)
// ---------------------------------------------------------------------------

namespace {
constexpr int kB = 8192;
constexpr int kN = 4;
constexpr int kC = 2048;
constexpr int kThreads = 256;
constexpr int kC4 = kC / 4;            // 512 float4 per stream per row
constexpr int kVec = kC4 / kThreads;   // 2 float4 chunks per thread
constexpr float kEps = 1e-6f;
constexpr unsigned kFull = 0xFFFFFFFFu;
}

__global__ __launch_bounds__(kThreads, 4) void mhc_fused_kernel(
    const float4* __restrict__ x,      // [B, n, C/4]
    const float4* __restrict__ w,      // [C/4]
    const float*  __restrict__ H_pre,  // [4]
    const float*  __restrict__ H_post, // [4]
    const float*  __restrict__ H_res,  // [4,4]
    float4* __restrict__ out) {        // [B, n, C/4]
    const int b = blockIdx.x;
    const int t = threadIdx.x;
    const int lane = t & 31;
    const int wid = t >> 5;

    __shared__ float s_warp[kThreads / 32];

    const size_t base = (size_t)b * (kN * kC4);

    // ---- Phase 1 (FIRST): front-batched loads — all 4 streams, 8 LDG.128 ---
    float xr[kN][kVec * 4];
#pragma unroll
    for (int k = 0; k < kVec; ++k) {
        const int c4 = t + k * kThreads;
#pragma unroll
        for (int n = 0; n < kN; ++n) {
            float4 v = x[base + (size_t)n * kC4 + c4];
            xr[n][k * 4 + 0] = v.x;
            xr[n][k * 4 + 1] = v.y;
            xr[n][k * 4 + 2] = v.z;
            xr[n][k * 4 + 3] = v.w;
        }
    }

    // ---- Phase 0 (hidden behind the LDGs): per-warp Sinkhorn + activations.
    // Lane l (<16) owns P[l/4][l%4]. Row sums via butterfly offsets {1,2},
    // column sums via {4,8}. Lanes 16-31 run with p=exp(0)=1; their
    // butterflies stay in the upper half and never pollute lanes 0-15.
    // Every warp computes its own copy -> no barrier, no smem.
    float pv;
    {
        float h = (lane < 16) ? H_res[lane] : 0.0f;
        float p = expf(h);
#pragma unroll
        for (int it = 0; it < 3; ++it) {
            float s = p;
            s += __shfl_xor_sync(kFull, s, 1);
            s += __shfl_xor_sync(kFull, s, 2);
            p = p / (s + kEps);          // row normalize
            s = p;
            s += __shfl_xor_sync(kFull, s, 4);
            s += __shfl_xor_sync(kFull, s, 8);
            p = p / (s + kEps);          // column normalize
        }
        pv = p;                          // lanes<16: M[lane/4][lane%4]
        if (lane >= 16 && lane < 20)
            pv = 1.0f / (1.0f + expf(-H_pre[lane - 16]));
        else if (lane >= 20 && lane < 24)
            pv = 2.0f / (1.0f + expf(-H_post[lane - 20]));
    }

    const float hp0 = __shfl_sync(kFull, pv, 16);
    const float hp1 = __shfl_sync(kFull, pv, 17);
    const float hp2 = __shfl_sync(kFull, pv, 18);
    const float hp3 = __shfl_sync(kFull, pv, 19);

    // ---- Phase 2: aggregate streams; round through bf16; sum of squares ----
    float y[kVec * 4];                   // holds bf16(agg) until finished below
    float lsum = 0.0f;
#pragma unroll
    for (int e = 0; e < kVec * 4; ++e) {
        float a = hp0 * xr[0][e];
        a = fmaf(hp1, xr[1][e], a);
        a = fmaf(hp2, xr[2][e], a);
        a = fmaf(hp3, xr[3][e], a);
        float ab = __bfloat162float(__float2bfloat16_rn(a));
        y[e] = ab;
        lsum = fmaf(ab, ab, lsum);
    }

    // ---- Phase 3: block reduction over C=2048 — ONE barrier ----------------
#pragma unroll
    for (int off = 16; off > 0; off >>= 1)
        lsum += __shfl_xor_sync(kFull, lsum, off);
    if (lane == 0) s_warp[wid] = lsum;
    __syncthreads();
    float ssum = 0.0f;
#pragma unroll
    for (int i = 0; i < kThreads / 32; ++i) ssum += s_warp[i];
    const float rinv = rsqrtf(ssum * (1.0f / (float)kC) + kEps);

    // ---- Phase 4: finish y in place. w loaded now (L1/L2-resident),
    //      its registers overlap dead aggregation temps.
#pragma unroll
    for (int k = 0; k < kVec; ++k) {
        float4 wv = w[t + k * kThreads];
        y[k * 4 + 0] *= rinv * __bfloat162float(__float2bfloat16_rn(wv.x));
        y[k * 4 + 1] *= rinv * __bfloat162float(__float2bfloat16_rn(wv.y));
        y[k * 4 + 2] *= rinv * __bfloat162float(__float2bfloat16_rn(wv.z));
        y[k * 4 + 3] *= rinv * __bfloat162float(__float2bfloat16_rn(wv.w));
    }

    // ---- Phase 5: mix + combine. One M row (+hpost) live at a time,
    //      fetched by warp shuffle from pv. ---------------------------------
#pragma unroll
    for (int i = 0; i < kN; ++i) {
        const float m0 = __shfl_sync(kFull, pv, i * 4 + 0);
        const float m1 = __shfl_sync(kFull, pv, i * 4 + 1);
        const float m2 = __shfl_sync(kFull, pv, i * 4 + 2);
        const float m3 = __shfl_sync(kFull, pv, i * 4 + 3);
        const float hpost_i = __shfl_sync(kFull, pv, 20 + i);
#pragma unroll
        for (int k = 0; k < kVec; ++k) {
            const int c4 = t + k * kThreads;
            float r[4];
#pragma unroll
            for (int q = 0; q < 4; ++q) {
                const int e = k * 4 + q;
                float acc = hpost_i * y[e];
                acc = fmaf(m0, xr[0][e], acc);
                acc = fmaf(m1, xr[1][e], acc);
                acc = fmaf(m2, xr[2][e], acc);
                acc = fmaf(m3, xr[3][e], acc);
                r[q] = acc;
            }
            float4 o;
            o.x = r[0]; o.y = r[1]; o.z = r[2]; o.w = r[3];
            out[base + (size_t)i * kC4 + c4] = o;
        }
    }
}

// ---------------------------------------------------------------------------
// Launch. Inputs (metadata order): x, rmsnorm_weight, H_pre, H_post, H_res.
// Single graph node.
// ---------------------------------------------------------------------------
extern "C" void kernel_launch(void* const* d_in, const int* in_sizes, int n_in,
                              void* d_out, int out_size) {
    const float* x      = (const float*)d_in[0];
    const float* w      = (const float*)d_in[1];
    const float* H_pre  = (const float*)d_in[2];
    const float* H_post = (const float*)d_in[3];
    const float* H_res  = (const float*)d_in[4];
    float* out = (float*)d_out;

    mhc_fused_kernel<<<kB, kThreads>>>(
        (const float4*)x, (const float4*)w, H_pre, H_post, H_res,
        (float4*)out);
}